// round 1
// baseline (speedup 1.0000x reference)
#include <cuda_runtime.h>

// ---------------------------------------------------------------------------
// InterpolatingBSpline2d: 2D cubic B-spline interpolation.
//   Inputs:  u    (B=2e6, 2) float32 in [0,1]^2
//            data (C=4, 64, 64) float32
//   Output:  (B, C) float32
//
// Stage 1+2: compute spline coefficients (C, 66, 66) via two separable
// tridiagonal solves. The boundary rows of the system matrix eliminate
// analytically: x1 = d0, x64 = d63, x0 = 2*x1 - x2, x65 = 2*x64 - x63.
// The interior is a constant-coefficient (1/6, 2/3, 1/6) tridiagonal system
// of size 62 solved with the Thomas algorithm (one thread per RHS).
//
// Stage 3: per-point bicubic evaluation with the full coefficient table
// resident in shared memory, packed [x][y][channel] as float4.
// ---------------------------------------------------------------------------

#define M_GRID   64
#define NP2      66       // M + 2
#define NINNER   62       // interior tridiagonal size
#define NCH      4

__device__ float g_cx[NCH * NP2 * M_GRID];        // stage-1 intermediate (c, jx, my)
__device__ float g_coefs[NP2 * NP2 * NCH];        // final coefs, layout (x*66 + y)*4 + c

// Solve the 66-unknown natural-BC spline system for one 64-sample RHS.
// src: 64 samples at stride sstride. dst: 66 outputs at stride dstride.
// cp / invden: precomputed Thomas factors (shared per block).
__device__ __forceinline__ void spline_solve_1d(
    const float* __restrict__ src, int sstride,
    float* __restrict__ dst, int dstride,
    const float* __restrict__ cp, const float* __restrict__ invden)
{
    const float SIXTH = 1.0f / 6.0f;
    float d0 = src[0];
    float dp[NINNER];

    // forward sweep
    dp[0] = (src[sstride] - d0 * SIXTH) * invden[0];
#pragma unroll
    for (int m = 1; m <= 60; ++m)
        dp[m] = (src[(m + 1) * sstride] - dp[m - 1] * SIXTH) * invden[m];
    float d63 = src[63 * sstride];
    dp[61] = (src[62 * sstride] - d63 * SIXTH - dp[60] * SIXTH) * invden[61];

    // back substitution; z_m = x_{m+2}
    float z = dp[61];
    dst[65 * dstride] = 2.0f * d63 - z;   // x65 = 2*x64 - x63
    dst[64 * dstride] = d63;              // x64 = d63
    dst[63 * dstride] = z;                // x63
#pragma unroll
    for (int m = 60; m >= 0; --m) {
        z = dp[m] - cp[m] * z;
        dst[(m + 2) * dstride] = z;
    }
    dst[dstride] = d0;                    // x1 = d0
    dst[0] = 2.0f * d0 - z;               // x0 = 2*x1 - x2 (z holds x2)
}

__device__ __forceinline__ void compute_thomas_factors(float* cp, float* invden)
{
    if (threadIdx.x == 0) {
        const float B = 2.0f / 3.0f, A = 1.0f / 6.0f;
        float c = A / B;
        cp[0] = c;
        invden[0] = 1.0f / B;
        for (int m = 1; m < NINNER; ++m) {
            float den = B - A * c;
            float inv = 1.0f / den;
            c = A * inv;
            cp[m] = c;
            invden[m] = inv;
        }
    }
    __syncthreads();
}

// Stage 1: solve along x for every (channel, my) column. 256 threads.
__global__ void coef_stage1(const float* __restrict__ data)
{
    __shared__ float cp[NINNER], invden[NINNER];
    compute_thomas_factors(cp, invden);

    int t = threadIdx.x;                 // 0..255
    int c = t >> 6;
    int my = t & 63;
    // data[c][k][my], k stride = 64 floats
    spline_solve_1d(data + c * (M_GRID * M_GRID) + my, M_GRID,
                    g_cx + c * (NP2 * M_GRID) + my, M_GRID,
                    cp, invden);
}

// Stage 2: solve along y for every (channel, jx) row. 264 active threads.
__global__ void coef_stage2()
{
    __shared__ float cp[NINNER], invden[NINNER];
    compute_thomas_factors(cp, invden);

    int t = threadIdx.x;
    if (t < NCH * NP2) {
        int c = t / NP2;
        int jx = t % NP2;
        spline_solve_1d(g_cx + (c * NP2 + jx) * M_GRID, 1,
                        g_coefs + jx * (NP2 * NCH) + c, NCH,
                        cp, invden);
    }
}

// Stage 3: per-point bicubic evaluation with the table in shared memory.
__global__ void __launch_bounds__(256) interp_kernel(
    const float2* __restrict__ u, float4* __restrict__ out, int n)
{
    extern __shared__ float4 s[];   // 66*66 float4 = 69,696 bytes
    const float4* gt = reinterpret_cast<const float4*>(g_coefs);
    for (int i = threadIdx.x; i < NP2 * NP2; i += blockDim.x)
        s[i] = gt[i];
    __syncthreads();

    const float SIXTH = 1.0f / 6.0f;
    int stride = gridDim.x * blockDim.x;
    for (int i = blockIdx.x * blockDim.x + threadIdx.x; i < n; i += stride) {
        float2 p = u[i];
        float ux = p.x * 63.0f;
        float uy = p.y * 63.0f;

        float fx = floorf(ux);
        int   ix = (int)fx;
        float tx = ux - fx;
        if (ux < 0.0f)   { ix = 0;  tx = ux; }
        if (ux >= 62.0f) { ix = 62; tx = ux - 62.0f; }

        float fy = floorf(uy);
        int   iy = (int)fy;
        float ty = uy - fy;
        if (uy < 0.0f)   { iy = 0;  ty = uy; }
        if (uy >= 62.0f) { iy = 62; ty = uy - 62.0f; }

        float tx2 = tx * tx, tx3 = tx2 * tx;
        float wx0 = SIXTH * (-tx3 + 3.0f * tx2 - 3.0f * tx + 1.0f);
        float wx1 = SIXTH * (3.0f * tx3 - 6.0f * tx2 + 4.0f);
        float wx2 = SIXTH * (-3.0f * tx3 + 3.0f * tx2 + 3.0f * tx + 1.0f);
        float wx3 = SIXTH * tx3;

        float ty2 = ty * ty, ty3 = ty2 * ty;
        float wy0 = SIXTH * (-ty3 + 3.0f * ty2 - 3.0f * ty + 1.0f);
        float wy1 = SIXTH * (3.0f * ty3 - 6.0f * ty2 + 4.0f);
        float wy2 = SIXTH * (-3.0f * ty3 + 3.0f * ty2 + 3.0f * ty + 1.0f);
        float wy3 = SIXTH * ty3;

        float wxa0 = wx0, wxa1 = wx1, wxa2 = wx2, wxa3 = wx3;

        const float4* base = s + ix * NP2 + iy;
        float4 acc = make_float4(0.0f, 0.0f, 0.0f, 0.0f);
#pragma unroll
        for (int dx = 0; dx < 4; ++dx) {
            const float4* r = base + dx * NP2;
            float4 r0 = r[0], r1 = r[1], r2 = r[2], r3 = r[3];
            float vx = r0.x * wy0 + r1.x * wy1 + r2.x * wy2 + r3.x * wy3;
            float vy = r0.y * wy0 + r1.y * wy1 + r2.y * wy2 + r3.y * wy3;
            float vz = r0.z * wy0 + r1.z * wy1 + r2.z * wy2 + r3.z * wy3;
            float vw = r0.w * wy0 + r1.w * wy1 + r2.w * wy2 + r3.w * wy3;
            float w = (dx == 0) ? wxa0 : (dx == 1) ? wxa1 : (dx == 2) ? wxa2 : wxa3;
            acc.x += vx * w;
            acc.y += vy * w;
            acc.z += vz * w;
            acc.w += vw * w;
        }
        out[i] = acc;
    }
}

extern "C" void kernel_launch(void* const* d_in, const int* in_sizes, int n_in,
                              void* d_out, int out_size)
{
    const float2* u    = (const float2*)d_in[0];
    const float*  data = (const float*)d_in[1];
    int n = in_sizes[0] / 2;

    const int smem_bytes = NP2 * NP2 * (int)sizeof(float4);   // 69,696
    cudaFuncSetAttribute(interp_kernel,
                         cudaFuncAttributeMaxDynamicSharedMemorySize, smem_bytes);

    coef_stage1<<<1, 256>>>(data);
    coef_stage2<<<1, 288>>>();
    interp_kernel<<<444, 256, smem_bytes>>>(u, (float4*)d_out, n);
}